// round 17
// baseline (speedup 1.0000x reference)
#include <cuda_runtime.h>
#include <math.h>

// x, x_r : (1, 3, 32, 512, 512) float32
// size=64 -> hc=wc=32 ; 16x16 patches per frame ; t=32
// patch mean = sum(|x-x_r|)/(2*3072) ; out = log(mean_t(max_patches))
// Deferred scaling: out = log( sum_t(max_p sum|dx|) / (32*6144) )
//
// R15 slab kernel (best measured: 512 CTAs x 512 thr, CTA = (t,ph) = 32 full
// rows x 3 ch = six contiguous 64KB streams, fence-free join) plus a 2-deep
// REGISTER DOUBLE-BUFFER: next iteration's (a,b) issued before consuming the
// current pair -> steady 2-4 LDG.128 outstanding (no front-burst).

#define T_DIM 32
#define NCTA 512             // 32 t * 16 ph
#define HW 512
#define TSTRIDE (512u * 512u)
#define CSTRIDE (32u * 512u * 512u)

__device__ int          g_frame_max[T_DIM];   // float bits; >=0 so int order == float order
__device__ unsigned int g_done_count;

__device__ __forceinline__ float4 ldcs4(const float* p) {
    float4 v;
    asm volatile("ld.global.cs.v4.f32 {%0,%1,%2,%3}, [%4];"
                 : "=f"(v.x), "=f"(v.y), "=f"(v.z), "=f"(v.w) : "l"(p));
    return v;
}

__device__ __forceinline__ float abs4(const float4 a, const float4 b) {
    return fabsf(a.x - b.x) + fabsf(a.y - b.y)
         + fabsf(a.z - b.z) + fabsf(a.w - b.w);
}

__global__ __launch_bounds__(512, 4)
void patch_loss_kernel(const float* __restrict__ x, const float* __restrict__ xr,
                       float* __restrict__ out) {
    const int bid = blockIdx.x;
    const int t   = bid >> 4;
    const int ph  = bid & 15;
    const int tid = threadIdx.x;

    // 512 threads x float4 = 2048 floats = 4 rows per step; 8 steps = 32 rows.
    // Thread's float column is fixed -> pw = colf/32 fixed for the whole CTA.
    const int rowoff = tid >> 7;              // 0..3 row within each 4-row step
    const int colf   = (tid & 127) << 2;      // float column 0..508
    const size_t base = (size_t)t * TSTRIDE
                      + (size_t)(ph * 32 + rowoff) * HW
                      + (size_t)colf;
    const float* px = x  + base;
    const float* pr = xr + base;

    // iter k = c*8 + i  ->  offset = c*CSTRIDE + i*(4*HW)
    float acc = 0.0f;
    float4 a = ldcs4(px);
    float4 b = ldcs4(pr);
    #pragma unroll
    for (int k = 1; k < 24; ++k) {
        const int c = k >> 3;
        const int i = k & 7;
        const size_t off = (size_t)c * CSTRIDE + (size_t)i * (4u * HW);
        const float4 an = ldcs4(px + off);    // prefetch next
        const float4 bn = ldcs4(pr + off);
        acc += abs4(a, b);                    // consume current
        a = an; b = bn;
    }
    acc += abs4(a, b);

    // 8-lane segmented reduce: lanes sharing one pw
    acc += __shfl_xor_sync(0xFFFFFFFFu, acc, 4);
    acc += __shfl_xor_sync(0xFFFFFFFFu, acc, 2);
    acc += __shfl_xor_sync(0xFFFFFFFFu, acc, 1);

    // warp w (0..15): pw = (w&3)*4 + lane/8 ; row-group slot = w>>2
    __shared__ float s[16][4];
    const int wid = tid >> 5, lane = tid & 31;
    if ((lane & 7) == 0) {
        const int pw = ((wid & 3) << 2) + (lane >> 3);
        s[pw][wid >> 2] = acc;
    }
    __syncthreads();

    if (tid < 32) {
        unsigned int prev = 0;
        if (tid < 16) {                       // thread i owns patch (t, ph, pw=i)
            const float total = s[tid][0] + s[tid][1] + s[tid][2] + s[tid][3];
            asm volatile("red.global.max.s32 [%0], %1;"
                         :: "l"(&g_frame_max[t]), "r"(__float_as_int(total)) : "memory");
        }
        __syncwarp();
        if (tid == 0) {
            asm volatile("atom.release.gpu.global.add.u32 %0, [%1], 1;"
                         : "=r"(prev) : "l"(&g_done_count) : "memory");
        }
        prev = __shfl_sync(0xFFFFFFFFu, prev, 0);

        if (prev == NCTA - 1) {               // last CTA: finalize
            asm volatile("fence.acq_rel.gpu;" ::: "memory");
            float sum = __int_as_float(__ldcg(&g_frame_max[tid]));
            #pragma unroll
            for (int o = 16; o > 0; o >>= 1)
                sum += __shfl_xor_sync(0xFFFFFFFFu, sum, o);
            if (tid == 0) {
                *out = logf(sum / (32.0f * 6144.0f));
                g_done_count = 0u;            // re-arm for next replay
            }
            __syncwarp();
            g_frame_max[tid] = 0;             // re-arm (after reads)
        }
    }
}

extern "C" void kernel_launch(void* const* d_in, const int* in_sizes, int n_in,
                              void* d_out, int out_size) {
    const float* x  = (const float*)d_in[0];
    const float* xr = (const float*)d_in[1];
    patch_loss_kernel<<<NCTA, 512>>>(x, xr, (float*)d_out);
}